// round 14
// baseline (speedup 1.0000x reference)
#include <cuda_runtime.h>
#include <cuda_fp16.h>
#include <mma.h>
#include <math.h>

using namespace nvcuda;

#define NN 50000
#define NP 50048                  // padded to multiple of 128 (tile size)
#define EE 800000
#define GG 1024
#define DD 64
#define DIN 9
#define CAP 96                    // bucket capacity per node (max in-deg ~40)
#define NBLK ((NN + 255) / 256)   // 196
#define GTB  (NP / 128)           // 391 tensor-GEMM blocks

// ---------------- scratch (static device globals; no allocation) ------------
__device__ int      g_pos[NN];         // fill cursor; after fill = in-degree
__device__ float    g_dinv[NN];        // rsqrt(deg+1)
__device__ int      g_srcs[NN * CAP];  // bucketed CSR (padded to mult of 8 w/ NN)
__device__ __align__(16) __half g_t[NP * DD];  // ts[v] = (hs@W)[v]; pad rows stay 0
__device__ __align__(16) __half g_h[NP * DD];  // hs[v] = dinv*tanh(conv); pad rows 0
__device__ unsigned g_gmax[GG * DD];
__device__ float    g_gsum[GG * DD];
__device__ int      g_gcnt[GG];

// ---------------- setup -----------------------------------------------------
__global__ void k_init() {
    int i = blockIdx.x * blockDim.x + threadIdx.x;   // grid covers 65536
    if (i < NN) g_pos[i] = 0;
    if (i < GG * DD) { g_gmax[i] = 0u; g_gsum[i] = 0.f; }
    if (i < GG) g_gcnt[i] = 0;
}

// bucket scatter: 2 edges per thread
__global__ void k_fill(const int* __restrict__ ei) {
    int e2 = (blockIdx.x * blockDim.x + threadIdx.x) * 2;
    if (e2 < EE) {
        int2 s = *(const int2*)(ei + e2);            // sources
        int2 d = *(const int2*)(ei + EE + e2);       // destinations
        int p0 = atomicAdd(&g_pos[d.x], 1);
        int p1 = atomicAdd(&g_pos[d.y], 1);
        if (p0 < CAP) g_srcs[d.x * CAP + p0] = s.x;
        if (p1 < CAP) g_srcs[d.y * CAP + p1] = s.y;
    }
}

// dinv + graph counts + pad each bucket to a multiple of 8 with dummy node NN
__global__ void k_dinv(const int* __restrict__ batch) {
    int i = blockIdx.x * blockDim.x + threadIdx.x;
    if (i < NN) {
        int c = min(g_pos[i], CAP);
        int cntp = (c + 7) & ~7;                     // <= CAP (CAP mult of 8)
        for (int j = c; j < cntp; j++) g_srcs[i * CAP + j] = NN;
        g_dinv[i] = rsqrtf((float)(g_pos[i] + 1));
        atomicAdd(&g_gcnt[batch[i]], 1);
    }
}

// ---------------- tensor-core GEMM, layers 1-3: t = hs @ W ------------------
// hs is pre-scaled by dinv, so NO row scaling needed. Per-warp staging +
// per-warp epilogue; single block sync (after Wh).
__global__ __launch_bounds__(256) void k_gemmTC(const __half* __restrict__ A,
        const float* __restrict__ W, __half* __restrict__ tout) {
    __shared__ __half Wh[DD * 72];         // B: row-major k x n, ld 72
    __shared__ float  Os[8][16 * 72];      // per-warp fp32 staging
    int tid = threadIdx.x, wid = tid >> 5, lane = tid & 31;
    for (int i = tid; i < DD * DD; i += 256) {
        int k = i >> 6, n = i & 63;
        Wh[k * 72 + n] = __float2half(W[i]);
    }
    __syncthreads();
    int row0 = blockIdx.x * 128 + wid * 16;
    const __half* Ap = A + row0 * DD;

    wmma::fragment<wmma::accumulator, 16, 16, 16, float> c[4];
#pragma unroll
    for (int n = 0; n < 4; n++) wmma::fill_fragment(c[n], 0.f);
#pragma unroll
    for (int k = 0; k < 4; k++) {
        wmma::fragment<wmma::matrix_a, 16, 16, 16, __half, wmma::row_major> a;
        wmma::load_matrix_sync(a, Ap + k * 16, DD);
#pragma unroll
        for (int n = 0; n < 4; n++) {
            wmma::fragment<wmma::matrix_b, 16, 16, 16, __half, wmma::row_major> b;
            wmma::load_matrix_sync(b, Wh + k * 16 * 72 + n * 16, 72);
            wmma::mma_sync(c[n], a, b, c[n]);
        }
    }
#pragma unroll
    for (int n = 0; n < 4; n++)
        wmma::store_matrix_sync(&Os[wid][n * 16], c[n], 72, wmma::mem_row_major);
    __syncwarp();
    // per-warp epilogue: pure fp32 -> fp16 convert + vector store
    for (int t = lane; t < 128; t += 32) {           // 16 rows x 8 col-chunks
        int r = t >> 3, ch = t & 7;
        int node = row0 + r;
        if (node >= NN) continue;
        const float* src = &Os[wid][r * 72 + ch * 8];
        __half2 h0 = __floats2half2_rn(src[0], src[1]);
        __half2 h1 = __floats2half2_rn(src[2], src[3]);
        __half2 h2 = __floats2half2_rn(src[4], src[5]);
        __half2 h3 = __floats2half2_rn(src[6], src[7]);
        uint4 o;
        o.x = *(unsigned*)&h0; o.y = *(unsigned*)&h1;
        o.z = *(unsigned*)&h2; o.w = *(unsigned*)&h3;
        *(uint4*)(tout + node * DD + ch * 8) = o;
    }
}

// ---------------- tensor-core GEMM, layer 0: t0 = (dinv*x) @ W0 -------------
// K = 9 padded to 16; A staged fp32->fp16 per warp, pre-scaled by dinv.
__global__ __launch_bounds__(256) void k_gemmTC9(const float* __restrict__ x,
        const float* __restrict__ W, __half* __restrict__ tout) {
    __shared__ __half Wh[16 * 72];
    __shared__ __half Ax[8][16 * 24];      // per-warp A patch, ld 24
    __shared__ float  Os[8][16 * 72];
    int tid = threadIdx.x, wid = tid >> 5, lane = tid & 31;
    for (int i = tid; i < 16 * DD; i += 256) {
        int k = i >> 6, n = i & 63;
        Wh[k * 72 + n] = (k < DIN) ? __float2half(W[k * DD + n])
                                   : __float2half(0.f);
    }
    int row0 = blockIdx.x * 128 + wid * 16;
    // per-warp A staging: 16 rows x 16 k (pad), 8 elements per lane
    {
        int r = lane >> 1, k0 = (lane & 1) * 8;
        int node = row0 + r;
        float di = (node < NN) ? g_dinv[node] : 0.f;
#pragma unroll
        for (int k = 0; k < 8; k++) {
            int kk = k0 + k;
            float v = (node < NN && kk < DIN) ? di * x[node * DIN + kk] : 0.f;
            Ax[wid][r * 24 + kk] = __float2half(v);
        }
    }
    __syncthreads();                        // Wh visible to all warps

    wmma::fragment<wmma::accumulator, 16, 16, 16, float> c[4];
#pragma unroll
    for (int n = 0; n < 4; n++) wmma::fill_fragment(c[n], 0.f);
    wmma::fragment<wmma::matrix_a, 16, 16, 16, __half, wmma::row_major> a;
    wmma::load_matrix_sync(a, Ax[wid], 24);
#pragma unroll
    for (int n = 0; n < 4; n++) {
        wmma::fragment<wmma::matrix_b, 16, 16, 16, __half, wmma::row_major> b;
        wmma::load_matrix_sync(b, Wh + n * 16, 72);
        wmma::mma_sync(c[n], a, b, c[n]);
    }
#pragma unroll
    for (int n = 0; n < 4; n++)
        wmma::store_matrix_sync(&Os[wid][n * 16], c[n], 72, wmma::mem_row_major);
    __syncwarp();
    for (int t = lane; t < 128; t += 32) {
        int r = t >> 3, ch = t & 7;
        int node = row0 + r;
        if (node >= NN) continue;
        const float* src = &Os[wid][r * 72 + ch * 8];
        __half2 h0 = __floats2half2_rn(src[0], src[1]);
        __half2 h1 = __floats2half2_rn(src[2], src[3]);
        __half2 h2 = __floats2half2_rn(src[4], src[5]);
        __half2 h3 = __floats2half2_rn(src[6], src[7]);
        uint4 o;
        o.x = *(unsigned*)&h0; o.y = *(unsigned*)&h1;
        o.z = *(unsigned*)&h2; o.w = *(unsigned*)&h3;
        *(uint4*)(tout + node * DD + ch * 8) = o;
    }
}

// ---------------- aggregation + bias + tanh epilogue -------------------------
// tin holds ts[v] = (hs@W)[v] = dinv[v-scaled product].
// h[v] = tanh( dinv[v]*(sum_s ts[s] + ts[v]) + b )
// POOL=0: write hs = dinv*h (fp16).  POOL=1: pool unscaled h.
template <int POOL>
__global__ void k_aggE(const __half* __restrict__ tin, __half* __restrict__ hout,
                       const float* __restrict__ b, const int* __restrict__ batch) {
    int w = (blockIdx.x * blockDim.x + threadIdx.x) >> 5;
    int lane = threadIdx.x & 31;
    if (w >= NN) return;
    int grp = lane >> 3;          // edge-pair slot within octet (0..3)
    int sub = lane & 7;           // dim-chunk (8 halves)
    int start = w * CAP;
    int c = min(g_pos[w], CAP);
    int cntp = (c + 7) & ~7;      // padded count (multiple of 8)
    const uint4* __restrict__ F = (const uint4*)tin;   // node row = 8 uint4
    float acc[8];
#pragma unroll
    for (int j = 0; j < 8; j++) acc[j] = 0.f;

    for (int base = 0; base < cntp; base += 32) {
        int m = min(32, cntp - base);                 // multiple of 8
        int sl = (lane < m) ? g_srcs[start + base + lane] : 0;
        for (int i = 0; i < m; i += 8) {
            int e = i + (grp << 1);
            int s0 = __shfl_sync(0xffffffffu, sl, e);
            int s1 = __shfl_sync(0xffffffffu, sl, e + 1);
            uint4 v0 = F[s0 * 8 + sub];
            uint4 v1 = F[s1 * 8 + sub];
            __half2 p0 = __hadd2(*(const __half2*)&v0.x, *(const __half2*)&v1.x);
            __half2 p1 = __hadd2(*(const __half2*)&v0.y, *(const __half2*)&v1.y);
            __half2 p2 = __hadd2(*(const __half2*)&v0.z, *(const __half2*)&v1.z);
            __half2 p3 = __hadd2(*(const __half2*)&v0.w, *(const __half2*)&v1.w);
            float2 f0 = __half22float2(p0), f1 = __half22float2(p1);
            float2 f2 = __half22float2(p2), f3 = __half22float2(p3);
            acc[0] += f0.x; acc[1] += f0.y;
            acc[2] += f1.x; acc[3] += f1.y;
            acc[4] += f2.x; acc[5] += f2.y;
            acc[6] += f3.x; acc[7] += f3.y;
        }
    }
#pragma unroll
    for (int j = 0; j < 8; j++) {
        acc[j] += __shfl_xor_sync(0xffffffffu, acc[j], 8);
        acc[j] += __shfl_xor_sync(0xffffffffu, acc[j], 16);
    }
    if (grp == 0) {                                   // lanes 0..7 finish node
        uint4 v = F[w * 8 + sub];                     // self term ts[v]
        float2 f0 = __half22float2(*(const __half2*)&v.x);
        float2 f1 = __half22float2(*(const __half2*)&v.y);
        float2 f2 = __half22float2(*(const __half2*)&v.z);
        float2 f3 = __half22float2(*(const __half2*)&v.w);
        acc[0] += f0.x; acc[1] += f0.y;
        acc[2] += f1.x; acc[3] += f1.y;
        acc[4] += f2.x; acc[5] += f2.y;
        acc[6] += f3.x; acc[7] += f3.y;
        float di = g_dinv[w];
        float4 b0 = *(const float4*)(b + sub * 8);
        float4 b1 = *(const float4*)(b + sub * 8 + 4);
        float hv[8];
        hv[0] = tanhf(fmaf(di, acc[0], b0.x));
        hv[1] = tanhf(fmaf(di, acc[1], b0.y));
        hv[2] = tanhf(fmaf(di, acc[2], b0.z));
        hv[3] = tanhf(fmaf(di, acc[3], b0.w));
        hv[4] = tanhf(fmaf(di, acc[4], b1.x));
        hv[5] = tanhf(fmaf(di, acc[5], b1.y));
        hv[6] = tanhf(fmaf(di, acc[6], b1.z));
        hv[7] = tanhf(fmaf(di, acc[7], b1.w));
        if (POOL) {
            int g = batch[w] * DD + sub * 8;
#pragma unroll
            for (int j = 0; j < 8; j++) {
                float xv = hv[j];
                unsigned enc = (xv >= 0.f) ? (__float_as_uint(xv) | 0x80000000u)
                                           : ~__float_as_uint(xv);
                atomicMax(&g_gmax[g + j], enc);
                atomicAdd(&g_gsum[g + j], xv);
            }
        } else {
            uint4 o;                                  // store hs = dinv*h
            *(__half2*)&o.x = __floats2half2_rn(di * hv[0], di * hv[1]);
            *(__half2*)&o.y = __floats2half2_rn(di * hv[2], di * hv[3]);
            *(__half2*)&o.z = __floats2half2_rn(di * hv[4], di * hv[5]);
            *(__half2*)&o.w = __floats2half2_rn(di * hv[6], di * hv[7]);
            ((uint4*)hout)[w * 8 + sub] = o;
        }
    }
}

// ---------------- readout ----------------------------------------------------
__global__ void k_out(const float* __restrict__ Wout, const float* __restrict__ bout,
                      float* __restrict__ out) {
    int g = blockIdx.x;
    int lane = threadIdx.x;
    float cnt = fmaxf((float)g_gcnt[g], 1.f);
    float s = 0.f;
    for (int f = lane; f < DD; f += 32) {
        unsigned e = g_gmax[g * DD + f];
        float mx = (e & 0x80000000u) ? __uint_as_float(e & 0x7FFFFFFFu)
                                     : __uint_as_float(~e);
        float mn = g_gsum[g * DD + f] / cnt;
        s += mx * Wout[f] + mn * Wout[DD + f];
    }
#pragma unroll
    for (int o = 16; o > 0; o >>= 1) s += __shfl_down_sync(0xFFFFFFFFu, s, o);
    if (lane == 0) out[g] = s + bout[0];
}

// ---------------- launch ----------------------------------------------------
extern "C" void kernel_launch(void* const* d_in, const int* in_sizes, int n_in,
                              void* d_out, int out_size) {
    const float* x     = (const float*)d_in[0];
    const int*   ei    = (const int*)d_in[1];
    const int*   batch = (const int*)d_in[2];
    const float* W0    = (const float*)d_in[3];
    const float* b0    = (const float*)d_in[4];
    const float* W1    = (const float*)d_in[5];
    const float* b1    = (const float*)d_in[6];
    const float* W2    = (const float*)d_in[7];
    const float* b2    = (const float*)d_in[8];
    const float* W3    = (const float*)d_in[9];
    const float* b3    = (const float*)d_in[10];
    const float* Wout  = (const float*)d_in[11];
    const float* bout  = (const float*)d_in[12];
    float* out = (float*)d_out;

    __half *tp, *hp;
    cudaGetSymbolAddress((void**)&tp, g_t);
    cudaGetSymbolAddress((void**)&hp, g_h);

    const int EB2  = (EE / 2 + 255) / 256;    // 1563 (2 edges/thread)
    const int AGGB = (NN * 32 + 255) / 256;   // 6250 (warp per node)

    k_init<<<256, 256>>>();
    k_fill<<<EB2, 256>>>(ei);
    k_dinv<<<NBLK, 256>>>(batch);

    // transform (tensor cores, scale-free) then aggregate (octet gather)
    k_gemmTC9<<<GTB, 256>>>(x, W0, tp);               // t0 = (dinv*x)@W0
    k_aggE<0><<<AGGB, 256>>>(tp, hp, b0, nullptr);    // hs1
    k_gemmTC<<<GTB, 256>>>(hp, W1, tp);               // t1 = hs1@W1
    k_aggE<0><<<AGGB, 256>>>(tp, hp, b1, nullptr);    // hs2
    k_gemmTC<<<GTB, 256>>>(hp, W2, tp);               // t2
    k_aggE<0><<<AGGB, 256>>>(tp, hp, b2, nullptr);    // hs3
    k_gemmTC<<<GTB, 256>>>(hp, W3, tp);               // t3
    k_aggE<1><<<AGGB, 256>>>(tp, nullptr, b3, batch); // h4 + fused pooling

    k_out<<<GG, 32>>>(Wout, bout, out);
}

// round 15
// speedup vs baseline: 1.0920x; 1.0920x over previous
#include <cuda_runtime.h>
#include <cuda_fp16.h>
#include <mma.h>
#include <math.h>

using namespace nvcuda;

#define NN 50000
#define NP 50048                  // padded to multiple of 128 (tile size)
#define EE 800000
#define GG 1024
#define DD 64
#define DIN 9
#define CAP 96                    // bucket capacity per node (max in-deg ~40)
#define NBLK ((NN + 255) / 256)   // 196
#define GTB  (NP / 128)           // 391 tensor-GEMM blocks

// ---------------- scratch (static device globals; no allocation) ------------
__device__ int      g_pos[NN];         // fill cursor; after fill = in-degree
__device__ int      g_srcs[NN * CAP];  // bucketed CSR
__device__ __align__(16) __half g_t[NP * DD];  // (hs@W); pad rows (incl. NN) stay 0
__device__ __align__(16) __half g_h[NP * DD];  // hs or h4; pad rows stay 0

// ---------------- setup -----------------------------------------------------
__global__ void k_init() {
    int i = blockIdx.x * blockDim.x + threadIdx.x;
    if (i < NN) g_pos[i] = 0;
}

// bucket scatter: 2 edges per thread
__global__ void k_fill(const int* __restrict__ ei) {
    int e2 = (blockIdx.x * blockDim.x + threadIdx.x) * 2;
    if (e2 < EE) {
        int2 s = *(const int2*)(ei + e2);            // sources
        int2 d = *(const int2*)(ei + EE + e2);       // destinations
        int p0 = atomicAdd(&g_pos[d.x], 1);
        int p1 = atomicAdd(&g_pos[d.y], 1);
        if (p0 < CAP) g_srcs[d.x * CAP + p0] = s.x;
        if (p1 < CAP) g_srcs[d.y * CAP + p1] = s.y;
    }
}

// ---------------- tensor-core GEMM, layers 1-3: t = hs @ W ------------------
__global__ __launch_bounds__(256) void k_gemmTC(const __half* __restrict__ A,
        const float* __restrict__ W, __half* __restrict__ tout) {
    __shared__ __half Wh[DD * 72];         // B: row-major k x n, ld 72
    __shared__ float  Os[8][16 * 72];      // per-warp fp32 staging
    int tid = threadIdx.x, wid = tid >> 5, lane = tid & 31;
    for (int i = tid; i < DD * DD; i += 256) {
        int k = i >> 6, n = i & 63;
        Wh[k * 72 + n] = __float2half(W[i]);
    }
    __syncthreads();
    int row0 = blockIdx.x * 128 + wid * 16;
    const __half* Ap = A + row0 * DD;

    wmma::fragment<wmma::accumulator, 16, 16, 16, float> c[4];
#pragma unroll
    for (int n = 0; n < 4; n++) wmma::fill_fragment(c[n], 0.f);
#pragma unroll
    for (int k = 0; k < 4; k++) {
        wmma::fragment<wmma::matrix_a, 16, 16, 16, __half, wmma::row_major> a;
        wmma::load_matrix_sync(a, Ap + k * 16, DD);
#pragma unroll
        for (int n = 0; n < 4; n++) {
            wmma::fragment<wmma::matrix_b, 16, 16, 16, __half, wmma::row_major> b;
            wmma::load_matrix_sync(b, Wh + k * 16 * 72 + n * 16, 72);
            wmma::mma_sync(c[n], a, b, c[n]);
        }
    }
#pragma unroll
    for (int n = 0; n < 4; n++)
        wmma::store_matrix_sync(&Os[wid][n * 16], c[n], 72, wmma::mem_row_major);
    __syncwarp();
    for (int t = lane; t < 128; t += 32) {           // 16 rows x 8 col-chunks
        int r = t >> 3, ch = t & 7;
        int node = row0 + r;
        if (node >= NN) continue;
        const float* src = &Os[wid][r * 72 + ch * 8];
        __half2 h0 = __floats2half2_rn(src[0], src[1]);
        __half2 h1 = __floats2half2_rn(src[2], src[3]);
        __half2 h2 = __floats2half2_rn(src[4], src[5]);
        __half2 h3 = __floats2half2_rn(src[6], src[7]);
        uint4 o;
        o.x = *(unsigned*)&h0; o.y = *(unsigned*)&h1;
        o.z = *(unsigned*)&h2; o.w = *(unsigned*)&h3;
        *(uint4*)(tout + node * DD + ch * 8) = o;
    }
}

// ---------------- tensor-core GEMM, layer 0: t0 = (dinv*x) @ W0 -------------
__global__ __launch_bounds__(256) void k_gemmTC9(const float* __restrict__ x,
        const float* __restrict__ W, __half* __restrict__ tout) {
    __shared__ __half Wh[16 * 72];
    __shared__ __half Ax[8][16 * 24];      // per-warp A patch, ld 24
    __shared__ float  Os[8][16 * 72];
    int tid = threadIdx.x, wid = tid >> 5, lane = tid & 31;
    for (int i = tid; i < 16 * DD; i += 256) {
        int k = i >> 6, n = i & 63;
        Wh[k * 72 + n] = (k < DIN) ? __float2half(W[k * DD + n])
                                   : __float2half(0.f);
    }
    int row0 = blockIdx.x * 128 + wid * 16;
    {
        int r = lane >> 1, k0 = (lane & 1) * 8;
        int node = row0 + r;
        float di = (node < NN) ? rsqrtf((float)(g_pos[node] + 1)) : 0.f;
#pragma unroll
        for (int k = 0; k < 8; k++) {
            int kk = k0 + k;
            float v = (node < NN && kk < DIN) ? di * x[node * DIN + kk] : 0.f;
            Ax[wid][r * 24 + kk] = __float2half(v);
        }
    }
    __syncthreads();

    wmma::fragment<wmma::accumulator, 16, 16, 16, float> c[4];
#pragma unroll
    for (int n = 0; n < 4; n++) wmma::fill_fragment(c[n], 0.f);
    wmma::fragment<wmma::matrix_a, 16, 16, 16, __half, wmma::row_major> a;
    wmma::load_matrix_sync(a, Ax[wid], 24);
#pragma unroll
    for (int n = 0; n < 4; n++) {
        wmma::fragment<wmma::matrix_b, 16, 16, 16, __half, wmma::row_major> b;
        wmma::load_matrix_sync(b, Wh + n * 16, 72);
        wmma::mma_sync(c[n], a, b, c[n]);
    }
#pragma unroll
    for (int n = 0; n < 4; n++)
        wmma::store_matrix_sync(&Os[wid][n * 16], c[n], 72, wmma::mem_row_major);
    __syncwarp();
    for (int t = lane; t < 128; t += 32) {
        int r = t >> 3, ch = t & 7;
        int node = row0 + r;
        if (node >= NN) continue;
        const float* src = &Os[wid][r * 72 + ch * 8];
        __half2 h0 = __floats2half2_rn(src[0], src[1]);
        __half2 h1 = __floats2half2_rn(src[2], src[3]);
        __half2 h2 = __floats2half2_rn(src[4], src[5]);
        __half2 h3 = __floats2half2_rn(src[6], src[7]);
        uint4 o;
        o.x = *(unsigned*)&h0; o.y = *(unsigned*)&h1;
        o.z = *(unsigned*)&h2; o.w = *(unsigned*)&h3;
        *(uint4*)(tout + node * DD + ch * 8) = o;
    }
}

// ---------------- aggregation + bias + tanh epilogue -------------------------
// tin: ts[v];  h[v] = tanh( dinv[v]*(sum_s ts[s] + ts[v]) + b )
// SCALE=1: store hs = dinv*h (feeds next GEMM). SCALE=0: store h (for pooling).
// Tail lanes load dummy zero-row NN -> no bucket padding needed.
template <int SCALE>
__global__ void k_aggE(const __half* __restrict__ tin, __half* __restrict__ hout,
                       const float* __restrict__ b) {
    int w = (blockIdx.x * blockDim.x + threadIdx.x) >> 5;
    int lane = threadIdx.x & 31;
    if (w >= NN) return;
    int grp = lane >> 3;          // edge-pair slot within octet (0..3)
    int sub = lane & 7;           // dim-chunk (8 halves)
    int start = w * CAP;
    int pos = g_pos[w];
    int cnt = min(pos, CAP);
    const uint4* __restrict__ F = (const uint4*)tin;   // node row = 8 uint4
    float acc[8];
#pragma unroll
    for (int j = 0; j < 8; j++) acc[j] = 0.f;

    for (int base = 0; base < cnt; base += 32) {
        int m = min(32, cnt - base);
        int sl = (lane < m) ? g_srcs[start + base + lane] : NN;  // NN = zero row
        int mo = (m + 7) & ~7;
        for (int i = 0; i < mo; i += 8) {
            int e = i + (grp << 1);
            int s0 = __shfl_sync(0xffffffffu, sl, e);
            int s1 = __shfl_sync(0xffffffffu, sl, e + 1);
            uint4 v0 = F[s0 * 8 + sub];
            uint4 v1 = F[s1 * 8 + sub];
            __half2 p0 = __hadd2(*(const __half2*)&v0.x, *(const __half2*)&v1.x);
            __half2 p1 = __hadd2(*(const __half2*)&v0.y, *(const __half2*)&v1.y);
            __half2 p2 = __hadd2(*(const __half2*)&v0.z, *(const __half2*)&v1.z);
            __half2 p3 = __hadd2(*(const __half2*)&v0.w, *(const __half2*)&v1.w);
            float2 f0 = __half22float2(p0), f1 = __half22float2(p1);
            float2 f2 = __half22float2(p2), f3 = __half22float2(p3);
            acc[0] += f0.x; acc[1] += f0.y;
            acc[2] += f1.x; acc[3] += f1.y;
            acc[4] += f2.x; acc[5] += f2.y;
            acc[6] += f3.x; acc[7] += f3.y;
        }
    }
#pragma unroll
    for (int j = 0; j < 8; j++) {
        acc[j] += __shfl_xor_sync(0xffffffffu, acc[j], 8);
        acc[j] += __shfl_xor_sync(0xffffffffu, acc[j], 16);
    }
    if (grp == 0) {                                   // lanes 0..7 finish node
        uint4 v = F[w * 8 + sub];                     // self term ts[v]
        float2 f0 = __half22float2(*(const __half2*)&v.x);
        float2 f1 = __half22float2(*(const __half2*)&v.y);
        float2 f2 = __half22float2(*(const __half2*)&v.z);
        float2 f3 = __half22float2(*(const __half2*)&v.w);
        acc[0] += f0.x; acc[1] += f0.y;
        acc[2] += f1.x; acc[3] += f1.y;
        acc[4] += f2.x; acc[5] += f2.y;
        acc[6] += f3.x; acc[7] += f3.y;
        float di = rsqrtf((float)(pos + 1));
        float4 b0 = *(const float4*)(b + sub * 8);
        float4 b1 = *(const float4*)(b + sub * 8 + 4);
        float hv[8];
        hv[0] = tanhf(fmaf(di, acc[0], b0.x));
        hv[1] = tanhf(fmaf(di, acc[1], b0.y));
        hv[2] = tanhf(fmaf(di, acc[2], b0.z));
        hv[3] = tanhf(fmaf(di, acc[3], b0.w));
        hv[4] = tanhf(fmaf(di, acc[4], b1.x));
        hv[5] = tanhf(fmaf(di, acc[5], b1.y));
        hv[6] = tanhf(fmaf(di, acc[6], b1.z));
        hv[7] = tanhf(fmaf(di, acc[7], b1.w));
        float sc = SCALE ? di : 1.f;
        uint4 o;
        *(__half2*)&o.x = __floats2half2_rn(sc * hv[0], sc * hv[1]);
        *(__half2*)&o.y = __floats2half2_rn(sc * hv[2], sc * hv[3]);
        *(__half2*)&o.z = __floats2half2_rn(sc * hv[4], sc * hv[5]);
        *(__half2*)&o.w = __floats2half2_rn(sc * hv[6], sc * hv[7]);
        ((uint4*)hout)[w * 8 + sub] = o;
    }
}

// ---------------- pooling + readout: one block per graph, no atomics --------
__global__ __launch_bounds__(64) void k_pool(const int* __restrict__ batch,
        const __half* __restrict__ h, const float* __restrict__ Wout,
        const float* __restrict__ bout, float* __restrict__ out) {
    int g = blockIdx.x;
    int t = threadIdx.x;                  // 64 threads, one dim each
    __shared__ int sb[2];
    if (t < 2) {                          // lower_bound(batch, g + t)
        int target = g + t;
        int lo = 0, hi = NN;
        while (lo < hi) {
            int mid = (lo + hi) >> 1;
            if (batch[mid] < target) lo = mid + 1; else hi = mid;
        }
        sb[t] = lo;
    }
    __syncthreads();
    int start = sb[0], end = sb[1];
    float mx = -1e30f, sm = 0.f;
    int n = start;
    for (; n + 4 <= end; n += 4) {        // 4-wide for MLP
        float v0 = __half2float(h[(n    ) * DD + t]);
        float v1 = __half2float(h[(n + 1) * DD + t]);
        float v2 = __half2float(h[(n + 2) * DD + t]);
        float v3 = __half2float(h[(n + 3) * DD + t]);
        mx = fmaxf(mx, fmaxf(fmaxf(v0, v1), fmaxf(v2, v3)));
        sm += (v0 + v1) + (v2 + v3);
    }
    for (; n < end; n++) {
        float v = __half2float(h[n * DD + t]);
        mx = fmaxf(mx, v); sm += v;
    }
    float cnt = fmaxf((float)(end - start), 1.f);
    float s = mx * Wout[t] + (sm / cnt) * Wout[DD + t];
    __shared__ float red[64];
    red[t] = s;
    __syncthreads();
    if (t < 32) {
        float v = red[t] + red[t + 32];
#pragma unroll
        for (int o = 16; o > 0; o >>= 1) v += __shfl_down_sync(0xffffffffu, v, o);
        if (t == 0) out[g] = v + bout[0];
    }
}

// ---------------- launch ----------------------------------------------------
extern "C" void kernel_launch(void* const* d_in, const int* in_sizes, int n_in,
                              void* d_out, int out_size) {
    const float* x     = (const float*)d_in[0];
    const int*   ei    = (const int*)d_in[1];
    const int*   batch = (const int*)d_in[2];
    const float* W0    = (const float*)d_in[3];
    const float* b0    = (const float*)d_in[4];
    const float* W1    = (const float*)d_in[5];
    const float* b1    = (const float*)d_in[6];
    const float* W2    = (const float*)d_in[7];
    const float* b2    = (const float*)d_in[8];
    const float* W3    = (const float*)d_in[9];
    const float* b3    = (const float*)d_in[10];
    const float* Wout  = (const float*)d_in[11];
    const float* bout  = (const float*)d_in[12];
    float* out = (float*)d_out;

    __half *tp, *hp;
    cudaGetSymbolAddress((void**)&tp, g_t);
    cudaGetSymbolAddress((void**)&hp, g_h);

    const int EB2  = (EE / 2 + 255) / 256;    // 1563 (2 edges/thread)
    const int AGGB = (NN * 32 + 255) / 256;   // 6250 (warp per node)

    k_init<<<NBLK, 256>>>();
    k_fill<<<EB2, 256>>>(ei);

    k_gemmTC9<<<GTB, 256>>>(x, W0, tp);            // t0 = (dinv*x)@W0
    k_aggE<1><<<AGGB, 256>>>(tp, hp, b0);          // hs1
    k_gemmTC<<<GTB, 256>>>(hp, W1, tp);            // t1 = hs1@W1
    k_aggE<1><<<AGGB, 256>>>(tp, hp, b1);          // hs2
    k_gemmTC<<<GTB, 256>>>(hp, W2, tp);            // t2
    k_aggE<1><<<AGGB, 256>>>(tp, hp, b2);          // hs3
    k_gemmTC<<<GTB, 256>>>(hp, W3, tp);            // t3
    k_aggE<0><<<AGGB, 256>>>(tp, hp, b3);          // h4 (unscaled, for pooling)

    k_pool<<<GG, 64>>>(batch, hp, Wout, bout, out);
}